// round 2
// baseline (speedup 1.0000x reference)
#include <cuda_runtime.h>

#define KSEG 512
#define DFEAT 256
#define HID 64
#define OUTC 32
#define MAXN 1048576

__device__ int g_hist[KSEG];
__device__ int g_offsets[KSEG + 1];
__device__ int g_cursor[KSEG];
__device__ int g_perm[MAXN];

// ---------------------------------------------------------------- zero
__global__ void zero_kernel() {
    int t = blockIdx.x * blockDim.x + threadIdx.x;
    if (t < KSEG) g_hist[t] = 0;
}

// ---------------------------------------------------------------- histogram
__global__ void hist_kernel(const int* __restrict__ ids, int n) {
    __shared__ int sh[KSEG];
    for (int i = threadIdx.x; i < KSEG; i += blockDim.x) sh[i] = 0;
    __syncthreads();
    int idx = blockIdx.x * blockDim.x + threadIdx.x;
    int stride = gridDim.x * blockDim.x;
    for (int i = idx; i < n; i += stride) {
        int s = ids[i];
        if (s >= 0) atomicAdd(&sh[s], 1);
    }
    __syncthreads();
    for (int i = threadIdx.x; i < KSEG; i += blockDim.x) {
        int v = sh[i];
        if (v) atomicAdd(&g_hist[i], v);
    }
}

// ---------------------------------------------------------------- scan (1 CTA, 512 thr)
__global__ void scan_kernel() {
    __shared__ int sh[KSEG];
    int t = threadIdx.x;
    int val = g_hist[t];
    sh[t] = val;
    __syncthreads();
    for (int off = 1; off < KSEG; off <<= 1) {
        int tmp = (t >= off) ? sh[t - off] : 0;
        int cur = sh[t];
        __syncthreads();
        sh[t] = cur + tmp;
        __syncthreads();
    }
    int incl = sh[t];
    int excl = incl - val;
    g_offsets[t] = excl;
    g_cursor[t] = excl;
    if (t == KSEG - 1) g_offsets[KSEG] = incl;
}

// ---------------------------------------------------------------- scatter perm
__global__ void scatter_kernel(const int* __restrict__ ids, int n) {
    int idx = blockIdx.x * blockDim.x + threadIdx.x;
    int stride = gridDim.x * blockDim.x;
    for (int i = idx; i < n; i += stride) {
        int s = ids[i];
        if (s >= 0) {
            int pos = atomicAdd(&g_cursor[s], 1);
            g_perm[pos] = i;
        }
    }
}

// ---------------------------------------------------------------- per-segment reduce
// 1 CTA per segment, 256 threads; thread t owns feature column t.
__global__ void reduce_kernel(const float* __restrict__ feat,
                              const float* __restrict__ coords,
                              float* __restrict__ emb,
                              float* __restrict__ cent) {
    int s = blockIdx.x;
    int start = g_offsets[s];
    int end   = g_offsets[s + 1];
    int cnt   = end - start;
    float denom = 1.0f / (float)(cnt > 0 ? cnt : 1);
    int t = threadIdx.x;

    float acc = 0.0f;
    int j = start;
    for (; j + 4 <= end; j += 4) {
        int i0 = g_perm[j];
        int i1 = g_perm[j + 1];
        int i2 = g_perm[j + 2];
        int i3 = g_perm[j + 3];
        float v0 = feat[(size_t)i0 * DFEAT + t];
        float v1 = feat[(size_t)i1 * DFEAT + t];
        float v2 = feat[(size_t)i2 * DFEAT + t];
        float v3 = feat[(size_t)i3 * DFEAT + t];
        acc += v0 + v1 + v2 + v3;
    }
    for (; j < end; j++)
        acc += feat[(size_t)g_perm[j] * DFEAT + t];
    emb[(size_t)s * DFEAT + t] = acc * denom;

    // coords: strided over threads, then block-reduce
    float cx = 0.f, cy = 0.f, cz = 0.f;
    for (int jj = start + t; jj < end; jj += 256) {
        int i = g_perm[jj];
        cx += coords[3 * (size_t)i + 0];
        cy += coords[3 * (size_t)i + 1];
        cz += coords[3 * (size_t)i + 2];
    }
    __shared__ float shx[256], shy[256], shz[256];
    shx[t] = cx; shy[t] = cy; shz[t] = cz;
    __syncthreads();
    for (int off = 128; off > 0; off >>= 1) {
        if (t < off) {
            shx[t] += shx[t + off];
            shy[t] += shy[t + off];
            shz[t] += shz[t + off];
        }
        __syncthreads();
    }
    if (t == 0) {
        cent[s * 3 + 0] = shx[0] * denom;
        cent[s * 3 + 1] = shy[0] * denom;
        cent[s * 3 + 2] = shz[0] * denom;
    }
}

// ---------------------------------------------------------------- tiny MLP
// 1 CTA per instance, 64 threads.
__global__ void mlp_kernel(const float* __restrict__ emb,
                           const float* __restrict__ W1,
                           const float* __restrict__ W2,
                           const float* __restrict__ W3,
                           const float* __restrict__ b3,
                           float* __restrict__ out) {
    int s = blockIdx.x;
    int t = threadIdx.x;  // 0..63
    __shared__ float e[DFEAT];
    __shared__ float h1[HID];
    __shared__ float h2[HID];
    for (int i = t; i < DFEAT; i += 64) e[i] = emb[(size_t)s * DFEAT + i];
    __syncthreads();
    float a = 0.f;
#pragma unroll 8
    for (int k = 0; k < DFEAT; k++) a += e[k] * W1[k * HID + t];
    h1[t] = fmaxf(a, 0.f);
    __syncthreads();
    float b = 0.f;
#pragma unroll 8
    for (int k = 0; k < HID; k++) b += h1[k] * W2[k * HID + t];
    h2[t] = fmaxf(b, 0.f);
    __syncthreads();
    if (t < OUTC) {
        float c = b3[t];
#pragma unroll 8
        for (int k = 0; k < HID; k++) c += h2[k] * W3[k * OUTC + t];
        out[(size_t)s * OUTC + t] = c;
    }
}

// ---------------------------------------------------------------- launch
extern "C" void kernel_launch(void* const* d_in, const int* in_sizes, int n_in,
                              void* d_out, int out_size) {
    const float* feat   = (const float*)d_in[0];
    const float* coords = (const float*)d_in[1];
    const int*   ids    = (const int*)d_in[2];

    // num_instances may arrive as a size-1 scalar array between ids and W1
    int wi = 3;
    if (n_in >= 8 && in_sizes[3] == 1) wi = 4;
    const float* W1 = (const float*)d_in[wi + 0];
    const float* W2 = (const float*)d_in[wi + 1];
    const float* W3 = (const float*)d_in[wi + 2];
    const float* b3 = (const float*)d_in[wi + 3];

    int n = in_sizes[0] / DFEAT;

    float* out  = (float*)d_out;
    float* emb  = out;                           // [K, 256]
    float* cent = out + (size_t)KSEG * DFEAT;    // [K, 3]
    float* mlp  = cent + (size_t)KSEG * 3;       // [K, 32]
    (void)out_size;

    zero_kernel<<<2, 256>>>();
    hist_kernel<<<592, 256>>>(ids, n);
    scan_kernel<<<1, KSEG>>>();
    scatter_kernel<<<592, 256>>>(ids, n);
    reduce_kernel<<<KSEG, 256>>>(feat, coords, emb, cent);
    mlp_kernel<<<KSEG, 64>>>(emb, W1, W2, W3, b3, mlp);
}

// round 3
// speedup vs baseline: 1.8555x; 1.8555x over previous
#include <cuda_runtime.h>

#define KSEG 512
#define DFEAT 256
#define HID 64
#define OUTC 32
#define MAXN 1048576
#define NB   592          // scatter/hist blocks (4 per SM on 148 SMs)

__device__ int g_blockhist[NB * KSEG];   // pass A: counts; pass B: per-(block,seg) base
__device__ int g_offsets[KSEG + 1];
__device__ int g_perm[MAXN];

// ---------------------------------------------------------------- pass A: per-block histogram
__global__ void __launch_bounds__(256) hist_kernel(const int* __restrict__ ids, int n, int chunk) {
    __shared__ int sh[KSEG];
    for (int i = threadIdx.x; i < KSEG; i += 256) sh[i] = 0;
    __syncthreads();
    int b = blockIdx.x;
    int lo = b * chunk;
    int hi = min(lo + chunk, n);
    for (int i = lo + threadIdx.x; i < hi; i += 256) {
        int s = ids[i];
        if (s >= 0) atomicAdd(&sh[s], 1);
    }
    __syncthreads();
    for (int i = threadIdx.x; i < KSEG; i += 256)
        g_blockhist[b * KSEG + i] = sh[i];
}

// ---------------------------------------------------------------- pass B: scan (1 CTA, 512 thr)
// Converts g_blockhist to within-segment block bases; computes segment offsets.
__global__ void __launch_bounds__(KSEG) scan_kernel() {
    int s = threadIdx.x;
    int run = 0;
#pragma unroll 8
    for (int b = 0; b < NB; b++) {
        int v = g_blockhist[b * KSEG + s];
        g_blockhist[b * KSEG + s] = run;
        run += v;
    }
    // run == count[s]; exclusive scan over segments
    __shared__ int sh[KSEG];
    sh[s] = run;
    __syncthreads();
    for (int off = 1; off < KSEG; off <<= 1) {
        int tmp = (s >= off) ? sh[s - off] : 0;
        int cur = sh[s];
        __syncthreads();
        sh[s] = cur + tmp;
        __syncthreads();
    }
    g_offsets[s] = sh[s] - run;
    if (s == KSEG - 1) g_offsets[KSEG] = sh[s];
}

// ---------------------------------------------------------------- pass C: scatter (shared cursors)
__global__ void __launch_bounds__(256) scatter_kernel(const int* __restrict__ ids, int n, int chunk) {
    __shared__ int cur[KSEG];
    int b = blockIdx.x;
    for (int i = threadIdx.x; i < KSEG; i += 256)
        cur[i] = g_offsets[i] + g_blockhist[b * KSEG + i];
    __syncthreads();
    int lo = b * chunk;
    int hi = min(lo + chunk, n);
    for (int i = lo + threadIdx.x; i < hi; i += 256) {
        int s = ids[i];
        if (s >= 0) {
            int pos = atomicAdd(&cur[s], 1);
            g_perm[pos] = i;
        }
    }
}

// ---------------------------------------------------------------- per-segment reduce (float4)
// 256 threads: 64 col-groups (float4 each) x 4 row slots; 2-deep unroll.
__global__ void __launch_bounds__(256) reduce_kernel(const float4* __restrict__ feat4,
                                                     const float* __restrict__ coords,
                                                     float* __restrict__ emb,
                                                     float* __restrict__ cent) {
    int s = blockIdx.x;
    int start = g_offsets[s];
    int end   = g_offsets[s + 1];
    int cnt   = end - start;
    float denom = 1.0f / (float)(cnt > 0 ? cnt : 1);
    int t  = threadIdx.x;
    int cg = t & 63;    // column group: cols [4cg, 4cg+3]
    int rs = t >> 6;    // row slot 0..3

    float4 acc = make_float4(0.f, 0.f, 0.f, 0.f);
    int j = start + rs;
    // 2-deep unroll: rows j and j+4 in flight
    for (; j + 4 < end; j += 8) {
        int i0 = g_perm[j];
        int i1 = g_perm[j + 4];
        float4 v0 = feat4[(size_t)i0 * 64 + cg];
        float4 v1 = feat4[(size_t)i1 * 64 + cg];
        acc.x += v0.x + v1.x; acc.y += v0.y + v1.y;
        acc.z += v0.z + v1.z; acc.w += v0.w + v1.w;
    }
    if (j < end) {
        int i0 = g_perm[j];
        float4 v0 = feat4[(size_t)i0 * 64 + cg];
        acc.x += v0.x; acc.y += v0.y; acc.z += v0.z; acc.w += v0.w;
    }

    __shared__ float4 shv[256];
    shv[t] = acc;
    __syncthreads();
    if (rs == 0) {
        float4 a = shv[cg], b = shv[cg + 64], c = shv[cg + 128], d = shv[cg + 192];
        float4 r;
        r.x = (a.x + b.x + c.x + d.x) * denom;
        r.y = (a.y + b.y + c.y + d.y) * denom;
        r.z = (a.z + b.z + c.z + d.z) * denom;
        r.w = (a.w + b.w + c.w + d.w) * denom;
        ((float4*)emb)[(size_t)s * 64 + cg] = r;
    }

    // coords: strided over threads, then block-reduce
    float cx = 0.f, cy = 0.f, cz = 0.f;
    for (int jj = start + t; jj < end; jj += 256) {
        int i = g_perm[jj];
        cx += coords[3 * (size_t)i + 0];
        cy += coords[3 * (size_t)i + 1];
        cz += coords[3 * (size_t)i + 2];
    }
    __shared__ float shx[256], shy[256], shz[256];
    shx[t] = cx; shy[t] = cy; shz[t] = cz;
    __syncthreads();
    for (int off = 128; off > 0; off >>= 1) {
        if (t < off) {
            shx[t] += shx[t + off];
            shy[t] += shy[t + off];
            shz[t] += shz[t + off];
        }
        __syncthreads();
    }
    if (t == 0) {
        cent[s * 3 + 0] = shx[0] * denom;
        cent[s * 3 + 1] = shy[0] * denom;
        cent[s * 3 + 2] = shz[0] * denom;
    }
}

// ---------------------------------------------------------------- tiny MLP (1 CTA / instance)
__global__ void __launch_bounds__(64) mlp_kernel(const float* __restrict__ emb,
                                                 const float* __restrict__ W1,
                                                 const float* __restrict__ W2,
                                                 const float* __restrict__ W3,
                                                 const float* __restrict__ b3,
                                                 float* __restrict__ out) {
    int s = blockIdx.x;
    int t = threadIdx.x;  // 0..63
    __shared__ float e[DFEAT];
    __shared__ float h1[HID];
    __shared__ float h2[HID];
    for (int i = t; i < DFEAT; i += 64) e[i] = emb[(size_t)s * DFEAT + i];
    __syncthreads();
    float a = 0.f;
#pragma unroll 8
    for (int k = 0; k < DFEAT; k++) a += e[k] * W1[k * HID + t];
    h1[t] = fmaxf(a, 0.f);
    __syncthreads();
    float b = 0.f;
#pragma unroll 8
    for (int k = 0; k < HID; k++) b += h1[k] * W2[k * HID + t];
    h2[t] = fmaxf(b, 0.f);
    __syncthreads();
    if (t < OUTC) {
        float c = b3[t];
#pragma unroll 8
        for (int k = 0; k < HID; k++) c += h2[k] * W3[k * OUTC + t];
        out[(size_t)s * OUTC + t] = c;
    }
}

// ---------------------------------------------------------------- launch
extern "C" void kernel_launch(void* const* d_in, const int* in_sizes, int n_in,
                              void* d_out, int out_size) {
    const float* feat   = (const float*)d_in[0];
    const float* coords = (const float*)d_in[1];
    const int*   ids    = (const int*)d_in[2];

    int wi = 3;
    if (n_in >= 8 && in_sizes[3] == 1) wi = 4;
    const float* W1 = (const float*)d_in[wi + 0];
    const float* W2 = (const float*)d_in[wi + 1];
    const float* W3 = (const float*)d_in[wi + 2];
    const float* b3 = (const float*)d_in[wi + 3];

    int n = in_sizes[0] / DFEAT;
    int chunk = (n + NB - 1) / NB;

    float* out  = (float*)d_out;
    float* emb  = out;                           // [K, 256]
    float* cent = out + (size_t)KSEG * DFEAT;    // [K, 3]
    float* mlp  = cent + (size_t)KSEG * 3;       // [K, 32]
    (void)out_size;

    hist_kernel<<<NB, 256>>>(ids, n, chunk);
    scan_kernel<<<1, KSEG>>>();
    scatter_kernel<<<NB, 256>>>(ids, n, chunk);
    reduce_kernel<<<KSEG, 256>>>((const float4*)feat, coords, emb, cent);
    mlp_kernel<<<KSEG, 64>>>(emb, W1, W2, W3, b3, mlp);
}

// round 6
// speedup vs baseline: 2.4245x; 1.3066x over previous
#include <cuda_runtime.h>

#define KSEG 512
#define DFEAT 256
#define HID 64
#define OUTC 32
#define MAXN 1048576
#define NB   592          // hist/scatter blocks (4 per SM on 148 SMs)
#define SPLIT 4           // reduce CTAs per segment
#define CPT 3             // blocks per thread in seg-scan (ceil(592/256))

__device__ int g_blockhist[NB * KSEG];   // pass A: counts; pass B: per-(block,seg) base
__device__ int g_count[KSEG];
__device__ int g_offsets[KSEG + 1];
__device__ int g_perm[MAXN];
__device__ float g_part[SPLIT * KSEG * DFEAT];   // feature partial sums
__device__ float g_cpart[SPLIT * KSEG * 3];      // coord partial sums

// ---------------------------------------------------------------- pass A: per-block histogram
__global__ void __launch_bounds__(256) hist_kernel(const int* __restrict__ ids, int n, int chunk) {
    __shared__ int sh[KSEG];
    for (int i = threadIdx.x; i < KSEG; i += 256) sh[i] = 0;
    __syncthreads();
    int b = blockIdx.x;
    int lo = b * chunk;
    int hi = min(lo + chunk, n);
    for (int i = lo + threadIdx.x; i < hi; i += 256) {
        int s = ids[i];
        if (s >= 0) atomicAdd(&sh[s], 1);
    }
    __syncthreads();
    for (int i = threadIdx.x; i < KSEG; i += 256)
        g_blockhist[b * KSEG + i] = sh[i];
}

// ---------------------------------------------------------------- pass B1: per-segment scan over blocks
// grid = KSEG (1 CTA per segment), 256 threads, CPT blocks/thread.
__global__ void __launch_bounds__(256) segscan_kernel() {
    int s = blockIdx.x;
    int t = threadIdx.x;
    int b0 = t * CPT;
    int v[CPT];
    int local = 0;
#pragma unroll
    for (int k = 0; k < CPT; k++) {
        int b = b0 + k;
        v[k] = (b < NB) ? g_blockhist[b * KSEG + s] : 0;
        local += v[k];
    }
    __shared__ int sh[256];
    sh[t] = local;
    __syncthreads();
    for (int off = 1; off < 256; off <<= 1) {
        int tmp = (t >= off) ? sh[t - off] : 0;
        int cur = sh[t];
        __syncthreads();
        sh[t] = cur + tmp;
        __syncthreads();
    }
    int run = sh[t] - local;   // exclusive prefix
#pragma unroll
    for (int k = 0; k < CPT; k++) {
        int b = b0 + k;
        if (b < NB) g_blockhist[b * KSEG + s] = run;
        run += v[k];
    }
    if (t == 255) g_count[s] = sh[255];
}

// ---------------------------------------------------------------- pass B2: segment-offset scan (1 CTA)
__global__ void __launch_bounds__(KSEG) offscan_kernel() {
    int s = threadIdx.x;
    int val = g_count[s];
    __shared__ int sh[KSEG];
    sh[s] = val;
    __syncthreads();
    for (int off = 1; off < KSEG; off <<= 1) {
        int tmp = (s >= off) ? sh[s - off] : 0;
        int cur = sh[s];
        __syncthreads();
        sh[s] = cur + tmp;
        __syncthreads();
    }
    g_offsets[s] = sh[s] - val;
    if (s == KSEG - 1) g_offsets[KSEG] = sh[s];
}

// ---------------------------------------------------------------- pass C: scatter (shared cursors)
__global__ void __launch_bounds__(256) scatter_kernel(const int* __restrict__ ids, int n, int chunk) {
    __shared__ int cur[KSEG];
    int b = blockIdx.x;
    for (int i = threadIdx.x; i < KSEG; i += 256)
        cur[i] = g_offsets[i] + g_blockhist[b * KSEG + i];
    __syncthreads();
    int lo = b * chunk;
    int hi = min(lo + chunk, n);
    for (int i = lo + threadIdx.x; i < hi; i += 256) {
        int s = ids[i];
        if (s >= 0) {
            int pos = atomicAdd(&cur[s], 1);
            g_perm[pos] = i;
        }
    }
}

// ---------------------------------------------------------------- split reduce (partials, no atomics)
// grid = KSEG*SPLIT. 256 threads: 64 col-groups (float4) x 4 row slots, 4-deep unroll.
__global__ void __launch_bounds__(256) reduce_kernel(const float4* __restrict__ feat4,
                                                     const float* __restrict__ coords) {
    int bid = blockIdx.x;
    int s = bid >> 2;          // segment
    int p = bid & (SPLIT - 1); // part
    int start = g_offsets[s];
    int end   = g_offsets[s + 1];
    int len   = end - start;
    int per   = (len + SPLIT - 1) / SPLIT;
    int lo = start + p * per;
    int hi = min(lo + per, end);

    int t  = threadIdx.x;
    int cg = t & 63;    // column group: cols [4cg, 4cg+3]
    int rs = t >> 6;    // row slot 0..3

    float4 acc = make_float4(0.f, 0.f, 0.f, 0.f);
    int j = lo + rs;
    // 4 rows in flight per thread (j, j+4, j+8, j+12)
    for (; j + 12 < hi; j += 16) {
        int i0 = g_perm[j];
        int i1 = g_perm[j + 4];
        int i2 = g_perm[j + 8];
        int i3 = g_perm[j + 12];
        float4 v0 = feat4[(size_t)i0 * 64 + cg];
        float4 v1 = feat4[(size_t)i1 * 64 + cg];
        float4 v2 = feat4[(size_t)i2 * 64 + cg];
        float4 v3 = feat4[(size_t)i3 * 64 + cg];
        acc.x += (v0.x + v1.x) + (v2.x + v3.x);
        acc.y += (v0.y + v1.y) + (v2.y + v3.y);
        acc.z += (v0.z + v1.z) + (v2.z + v3.z);
        acc.w += (v0.w + v1.w) + (v2.w + v3.w);
    }
    for (; j < hi; j += 4) {
        int i0 = g_perm[j];
        float4 v0 = feat4[(size_t)i0 * 64 + cg];
        acc.x += v0.x; acc.y += v0.y; acc.z += v0.z; acc.w += v0.w;
    }

    __shared__ float4 shv[256];
    shv[t] = acc;
    __syncthreads();
    if (rs == 0) {
        float4 a = shv[cg], b = shv[cg + 64], c = shv[cg + 128], d = shv[cg + 192];
        float4 r;
        r.x = (a.x + b.x) + (c.x + d.x);
        r.y = (a.y + b.y) + (c.y + d.y);
        r.z = (a.z + b.z) + (c.z + d.z);
        r.w = (a.w + b.w) + (c.w + d.w);
        ((float4*)g_part)[((size_t)p * KSEG + s) * 64 + cg] = r;
    }

    // coords partial
    float cx = 0.f, cy = 0.f, cz = 0.f;
    for (int jj = lo + t; jj < hi; jj += 256) {
        int i = g_perm[jj];
        cx += coords[3 * (size_t)i + 0];
        cy += coords[3 * (size_t)i + 1];
        cz += coords[3 * (size_t)i + 2];
    }
    __shared__ float shx[256], shy[256], shz[256];
    shx[t] = cx; shy[t] = cy; shz[t] = cz;
    __syncthreads();
    for (int off = 128; off > 0; off >>= 1) {
        if (t < off) {
            shx[t] += shx[t + off];
            shy[t] += shy[t + off];
            shz[t] += shz[t + off];
        }
        __syncthreads();
    }
    if (t == 0) {
        g_cpart[((size_t)p * KSEG + s) * 3 + 0] = shx[0];
        g_cpart[((size_t)p * KSEG + s) * 3 + 1] = shy[0];
        g_cpart[((size_t)p * KSEG + s) * 3 + 2] = shz[0];
    }
}

// ---------------------------------------------------------------- combine + centroid + MLP (fused)
// grid = KSEG, 256 threads.
__global__ void __launch_bounds__(256) combine_kernel(const float* __restrict__ W1,
                                                      const float* __restrict__ W2,
                                                      const float* __restrict__ W3,
                                                      const float* __restrict__ b3,
                                                      float* __restrict__ emb,
                                                      float* __restrict__ cent,
                                                      float* __restrict__ out) {
    int s = blockIdx.x;
    int t = threadIdx.x;
    int cnt = g_offsets[s + 1] - g_offsets[s];
    float denom = 1.0f / (float)(cnt > 0 ? cnt : 1);

    __shared__ float e[DFEAT];
    // each thread finalizes one feature column
    float v = 0.f;
#pragma unroll
    for (int p = 0; p < SPLIT; p++)
        v += g_part[((size_t)p * KSEG + s) * DFEAT + t];
    v *= denom;
    e[t] = v;
    emb[(size_t)s * DFEAT + t] = v;

    if (t < 3) {
        float c = 0.f;
#pragma unroll
        for (int p = 0; p < SPLIT; p++)
            c += g_cpart[((size_t)p * KSEG + s) * 3 + t];
        cent[s * 3 + t] = c * denom;
    }
    __syncthreads();

    __shared__ float h1[HID];
    __shared__ float h2[HID];
    if (t < HID) {
        float a = 0.f;
#pragma unroll 8
        for (int k = 0; k < DFEAT; k++) a += e[k] * W1[k * HID + t];
        h1[t] = fmaxf(a, 0.f);
    }
    __syncthreads();
    if (t < HID) {
        float b = 0.f;
#pragma unroll 8
        for (int k = 0; k < HID; k++) b += h1[k] * W2[k * HID + t];
        h2[t] = fmaxf(b, 0.f);
    }
    __syncthreads();
    if (t < OUTC) {
        float c = b3[t];
#pragma unroll 8
        for (int k = 0; k < HID; k++) c += h2[k] * W3[k * OUTC + t];
        out[(size_t)s * OUTC + t] = c;
    }
}

// ---------------------------------------------------------------- launch
extern "C" void kernel_launch(void* const* d_in, const int* in_sizes, int n_in,
                              void* d_out, int out_size) {
    const float* feat   = (const float*)d_in[0];
    const float* coords = (const float*)d_in[1];
    const int*   ids    = (const int*)d_in[2];

    int wi = 3;
    if (n_in >= 8 && in_sizes[3] == 1) wi = 4;
    const float* W1 = (const float*)d_in[wi + 0];
    const float* W2 = (const float*)d_in[wi + 1];
    const float* W3 = (const float*)d_in[wi + 2];
    const float* b3 = (const float*)d_in[wi + 3];

    int n = in_sizes[0] / DFEAT;
    int chunk = (n + NB - 1) / NB;

    float* out  = (float*)d_out;
    float* emb  = out;                           // [K, 256]
    float* cent = out + (size_t)KSEG * DFEAT;    // [K, 3]
    float* mlp  = cent + (size_t)KSEG * 3;       // [K, 32]
    (void)out_size;

    hist_kernel<<<NB, 256>>>(ids, n, chunk);
    segscan_kernel<<<KSEG, 256>>>();
    offscan_kernel<<<1, KSEG>>>();
    scatter_kernel<<<NB, 256>>>(ids, n, chunk);
    reduce_kernel<<<KSEG * SPLIT, 256>>>((const float4*)feat, coords);
    combine_kernel<<<KSEG, 256>>>(W1, W2, W3, b3, emb, cent, mlp);
}